// round 2
// baseline (speedup 1.0000x reference)
#include <cuda_runtime.h>
#include <math.h>
#include <stdint.h>

// Problem dims (fixed by the reference)
#define SEQ    32768
#define NHEAD  8
#define DIN    64
#define DHID   64
#define DOUT   64
#define DMODEL 512                 // NHEAD*DIN
#define NROWS  (SEQ*NHEAD)         // 262144
#define LCH    128                 // scan chunk length
#define NCH    (NROWS/LCH)         // 2048 chunks

// ---------------- scratch (static __device__, no allocations) ----------------
__device__ float g_x  [(size_t)NROWS*DIN];       // 64 MB
__device__ float g_g  [(size_t)NROWS*3*DHID];    // 192 MB
__device__ float g_fg [(size_t)NROWS*DHID];      // 64 MB
__device__ float g_hr [(size_t)NROWS*DHID];      // 64 MB
__device__ float g_ogr[(size_t)NROWS*DHID];      // 64 MB (pre-sigmoid)
__device__ float g_y  [(size_t)NROWS*DHID];      // 64 MB
__device__ float g_o  [(size_t)NROWS*DOUT];      // 64 MB
__device__ float g_aggA [NCH*DHID];
__device__ float g_aggB [NCH*DHID];
__device__ float g_carry[NCH*DHID];

// ---------------- generic tiled fp32 GEMM:  C = A(MxK) @ B(KxN) + bias ----------------
// BM=128, BN=64, BK=32, micro 8x4, 256 threads. Requires M%128==0, N%64==0, K%32==0.
template<int BM, int BN, int BK, int TM, int TN>
__global__ void __launch_bounds__(256) sgemm_bias(
    const float* __restrict__ A, const float* __restrict__ B,
    const float* __restrict__ bias, float* __restrict__ C,
    int M, int N, int K)
{
    constexpr int BKP = BK + 1;                 // pad: conflict-free column reads
    __shared__ float As[BM][BKP];
    __shared__ float Bs[BK][BN];
    constexpr int NT = (BM/TM)*(BN/TN);         // 256

    const int tid = threadIdx.x;
    const int tx  = tid % (BN/TN);              // 16 col groups
    const int ty  = tid / (BN/TN);              // 16 row groups
    const int row0 = blockIdx.y * BM;
    const int col0 = blockIdx.x * BN;

    float acc[TM][TN];
#pragma unroll
    for (int i = 0; i < TM; i++)
#pragma unroll
        for (int j = 0; j < TN; j++) acc[i][j] = 0.f;

    for (int k0 = 0; k0 < K; k0 += BK) {
        // load A tile (BM x BK), float4 along K, scalar-store into padded rows
#pragma unroll
        for (int li = 0; li < (BM*BK)/(NT*4); li++) {
            int flat = li*NT + tid;             // float4 index
            int m  = flat / (BK/4);
            int k4 = (flat % (BK/4)) * 4;
            float4 v = *(const float4*)(A + (size_t)(row0+m)*K + k0 + k4);
            As[m][k4+0] = v.x;
            As[m][k4+1] = v.y;
            As[m][k4+2] = v.z;
            As[m][k4+3] = v.w;
        }
        // load B tile (BK x BN), straight float4 copy
#pragma unroll
        for (int li = 0; li < (BK*BN)/(NT*4); li++) {
            int flat = li*NT + tid;
            int k  = flat / (BN/4);
            int n4 = (flat % (BN/4)) * 4;
            *(float4*)&Bs[k][n4] = *(const float4*)(B + (size_t)(k0+k)*N + col0 + n4);
        }
        __syncthreads();

#pragma unroll
        for (int k = 0; k < BK; k++) {
            float a[TM], b[TN];
#pragma unroll
            for (int i = 0; i < TM; i++) a[i] = As[ty*TM + i][k];
#pragma unroll
            for (int j = 0; j < TN; j += 4) {
                float4 v = *(float4*)&Bs[k][tx*TN + j];
                b[j] = v.x; b[j+1] = v.y; b[j+2] = v.z; b[j+3] = v.w;
            }
#pragma unroll
            for (int i = 0; i < TM; i++)
#pragma unroll
                for (int j = 0; j < TN; j++)
                    acc[i][j] = fmaf(a[i], b[j], acc[i][j]);
        }
        __syncthreads();
    }

#pragma unroll
    for (int i = 0; i < TM; i++) {
        int row = row0 + ty*TM + i;
#pragma unroll
        for (int j = 0; j < TN; j += 4) {
            int col = col0 + tx*TN + j;
            float4 o;
            o.x = acc[i][j+0] + bias[col+0];
            o.y = acc[i][j+1] + bias[col+1];
            o.z = acc[i][j+2] + bias[col+2];
            o.w = acc[i][j+3] + bias[col+3];
            *(float4*)(C + (size_t)row*N + col) = o;
        }
    }
}

// ---------------- elementwise gate transform ----------------
__device__ __forceinline__ float sigmoidf_(float x) { return 1.f / (1.f + expf(-x)); }

__global__ void gates_ew()
{
    int i  = blockIdx.x * blockDim.x + threadIdx.x;   // over NROWS*16 float4-groups
    int r  = i >> 4;
    int j4 = (i & 15) << 2;
    const float* gp = g_g + (size_t)r * (3*DHID);
    float4 a = *(const float4*)(gp + j4);              // pre-sigmoid fg
    float4 b = *(const float4*)(gp + DHID + j4);       // pre-sigmoid ig
    float4 c = *(const float4*)(gp + 2*DHID + j4);     // pre-tanh h
    float4 f, h;
    f.x = sigmoidf_(a.x); f.y = sigmoidf_(a.y); f.z = sigmoidf_(a.z); f.w = sigmoidf_(a.w);
    h.x = sigmoidf_(b.x) * tanhf(c.x);
    h.y = sigmoidf_(b.y) * tanhf(c.y);
    h.z = sigmoidf_(b.z) * tanhf(c.z);
    h.w = sigmoidf_(b.w) * tanhf(c.w);
    *(float4*)(g_fg + (size_t)r*DHID + j4) = f;
    *(float4*)(g_hr + (size_t)r*DHID + j4) = h;
}

// ---------------- chunked linear-recurrence scan ----------------
// c_t = fg_t * c_{t-1} + hr_t over the full NROWS sequence, per column (64 cols).
__global__ void scan_pass1()
{
    int b = blockIdx.x;
    int j = threadIdx.x;                          // column
    size_t base = (size_t)b * LCH * DHID + j;
    float A = 1.f, B = 0.f;
#pragma unroll 4
    for (int t = 0; t < LCH; t++) {
        size_t idx = base + (size_t)t * DHID;
        float a = g_fg[idx];
        float h = g_hr[idx];
        B = fmaf(B, a, h);
        A *= a;
    }
    g_aggA[b*DHID + j] = A;
    g_aggB[b*DHID + j] = B;
}

__global__ void scan_combine()
{
    int j = threadIdx.x;
    float c = 0.f;
    for (int b = 0; b < NCH; b++) {
        g_carry[b*DHID + j] = c;                  // exclusive carry-in
        c = fmaf(c, g_aggA[b*DHID + j], g_aggB[b*DHID + j]);
    }
}

__global__ void scan_apply()
{
    int b = blockIdx.x;
    int j = threadIdx.x;
    size_t base = (size_t)b * LCH * DHID + j;
    float c = g_carry[b*DHID + j];
#pragma unroll 4
    for (int t = 0; t < LCH; t++) {
        size_t idx = base + (size_t)t * DHID;
        c = fmaf(c, g_fg[idx], g_hr[idx]);
        float og = sigmoidf_(g_ogr[idx]);
        g_y[idx] = og * c;
    }
}

// ---------------- launch ----------------
extern "C" void kernel_launch(void* const* d_in, const int* in_sizes, int n_in,
                              void* d_out, int out_size)
{
    const float* inputs  = (const float*)d_in[0];
    const float* W_in    = (const float*)d_in[1];
    const float* b_in    = (const float*)d_in[2];
    const float* W_gates = (const float*)d_in[3];
    const float* b_gates = (const float*)d_in[4];
    const float* W_og    = (const float*)d_in[5];
    const float* b_og    = (const float*)d_in[6];
    const float* W_c     = (const float*)d_in[7];
    const float* b_c     = (const float*)d_in[8];
    const float* W_out   = (const float*)d_in[9];
    const float* b_out   = (const float*)d_in[10];
    float* out = (float*)d_out;

    float *px, *pg, *pogr, *py, *po;
    cudaGetSymbolAddress((void**)&px,   g_x);
    cudaGetSymbolAddress((void**)&pg,   g_g);
    cudaGetSymbolAddress((void**)&pogr, g_ogr);
    cudaGetSymbolAddress((void**)&py,   g_y);
    cudaGetSymbolAddress((void**)&po,   g_o);

    dim3 blk(256);

    // 1) x = inputs @ W_in + b_in           (32768 x 512 x 512)
    sgemm_bias<128,64,32,8,4><<<dim3(DMODEL/64, SEQ/128), blk>>>(
        inputs, W_in, b_in, px, SEQ, DMODEL, DMODEL);

    // 2) g = x' @ W_gates + b_gates         (262144 x 192 x 64), x' = x viewed (S*H, 64)
    sgemm_bias<128,64,32,8,4><<<dim3(3, NROWS/128), blk>>>(
        px, W_gates, b_gates, pg, NROWS, 3*DHID, DIN);

    // 3) og_raw = x' @ W_og + b_og          (262144 x 64 x 64)
    sgemm_bias<128,64,32,8,4><<<dim3(1, NROWS/128), blk>>>(
        px, W_og, b_og, pogr, NROWS, DHID, DIN);

    // 4) gate nonlinearities -> fg, hr
    gates_ew<<<(NROWS*16)/256, 256>>>();

    // 5-7) chunked scan over 262144 steps x 64 columns
    scan_pass1  <<<NCH, DHID>>>();
    scan_combine<<<1,   DHID>>>();
    scan_apply  <<<NCH, DHID>>>();

    // 8) o = y @ W_c + b_c                  (262144 x 64 x 64)
    sgemm_bias<128,64,32,8,4><<<dim3(1, NROWS/128), blk>>>(
        py, W_c, b_c, po, NROWS, DOUT, DHID);

    // 9) out = o'' @ W_out + b_out          (32768 x 512 x 512), o'' = o viewed (S, 512)
    sgemm_bias<128,64,32,8,4><<<dim3(DMODEL/64, SEQ/128), blk>>>(
        po, W_out, b_out, out, SEQ, DMODEL, DMODEL);
}

// round 4
// speedup vs baseline: 1.4214x; 1.4214x over previous
#include <cuda_runtime.h>
#include <cuda_bf16.h>
#include <math.h>
#include <stdint.h>

// Problem dims (fixed by the reference)
#define SEQ    32768
#define NHEAD  8
#define DIN    64
#define DHID   64
#define DOUT   64
#define DMODEL 512                 // NHEAD*DIN
#define NROWS  (SEQ*NHEAD)         // 262144
#define LCH    128                 // scan chunk length
#define NCH    (NROWS/LCH)         // 2048 chunks

// ---------------- scratch (static __device__, no allocations) ----------------
__device__ float g_x [(size_t)NROWS*DIN];       // 64 MB
__device__ float g_g [(size_t)NROWS*3*DHID];    // 192 MB
__device__ float g_fg[(size_t)NROWS*DHID];      // 64 MB
__device__ float g_hr[(size_t)NROWS*DHID];      // 64 MB
__device__ float g_og[(size_t)NROWS*DHID];      // 64 MB (post-sigmoid)
__device__ float g_y [(size_t)NROWS*DHID];      // 64 MB
__device__ float g_o [(size_t)NROWS*DOUT];      // 64 MB
__device__ float g_aggA [NCH*DHID];
__device__ float g_aggB [NCH*DHID];
__device__ float g_carry[NCH*DHID];

__device__ __forceinline__ float sigmoidf_(float x) { return 1.f / (1.f + expf(-x)); }

// ---------------- mma / ldmatrix primitives ----------------
__device__ __forceinline__ void ldsm4(uint32_t r[4], uint32_t a) {
    asm volatile("ldmatrix.sync.aligned.m8n8.x4.shared.b16 {%0,%1,%2,%3},[%4];"
        : "=r"(r[0]), "=r"(r[1]), "=r"(r[2]), "=r"(r[3]) : "r"(a));
}
__device__ __forceinline__ void ldsm4t(uint32_t r[4], uint32_t a) {
    asm volatile("ldmatrix.sync.aligned.m8n8.x4.trans.shared.b16 {%0,%1,%2,%3},[%4];"
        : "=r"(r[0]), "=r"(r[1]), "=r"(r[2]), "=r"(r[3]) : "r"(a));
}
__device__ __forceinline__ void mma16816(float c[4], const uint32_t a[4], const uint32_t b[2]) {
    asm volatile("mma.sync.aligned.m16n8k16.row.col.f32.bf16.bf16.f32 "
        "{%0,%1,%2,%3},{%4,%5,%6,%7},{%8,%9},{%0,%1,%2,%3};"
        : "+f"(c[0]), "+f"(c[1]), "+f"(c[2]), "+f"(c[3])
        : "r"(a[0]), "r"(a[1]), "r"(a[2]), "r"(a[3]), "r"(b[0]), "r"(b[1]));
}

__device__ __forceinline__ void split2(float x, float y, __nv_bfloat162& hi, __nv_bfloat162& lo) {
    __nv_bfloat16 hx = __float2bfloat16(x);
    __nv_bfloat16 hy = __float2bfloat16(y);
    __nv_bfloat16 lx = __float2bfloat16(x - __bfloat162float(hx));
    __nv_bfloat16 ly = __float2bfloat16(y - __bfloat162float(hy));
    hi.x = hx; hi.y = hy;
    lo.x = lx; lo.y = ly;
}

// ---------------- tensor-core GEMM with in-staging bf16 hi/lo split ----------------
// C = A(MxK fp32) @ B(KxN fp32) + bias, computed as Ah*Bh + Ah*Bl + Al*Bh (fp32 accum).
// BM=128, BN=64, BK=32; 256 threads = 8 warps (4 along M x 2 along N), warp tile 32x32.
// MODE 0: plain fp32 store; MODE 2: sigmoid then fp32 store.
template<int MODE>
__global__ void __launch_bounds__(256) gemm_tc(
    const float* __restrict__ A, const float* __restrict__ B,
    const float* __restrict__ bias, float* __restrict__ C,
    int M, int N, int K)
{
    constexpr int BM = 128, BN = 64, BK = 32;
    constexpr int SA = BK + 8;   // 40 bf16 per A row (80 B, 16B-aligned rows)
    constexpr int SB = BN + 8;   // 72 bf16 per B row (144 B)
    __shared__ __align__(16) __nv_bfloat16 sAh[BM*SA], sAl[BM*SA];
    __shared__ __align__(16) __nv_bfloat16 sBh[BK*SB], sBl[BK*SB];

    const int tid  = threadIdx.x;
    const int lane = tid & 31, warp = tid >> 5;
    const int wm = warp & 3;          // 0..3 along M (32 rows each)
    const int wn = warp >> 2;         // 0..1 along N (32 cols each)
    const int row0 = blockIdx.y * BM, col0 = blockIdx.x * BN;

    const uint32_t bAh = (uint32_t)__cvta_generic_to_shared(sAh);
    const uint32_t bAl = (uint32_t)__cvta_generic_to_shared(sAl);
    const uint32_t bBh = (uint32_t)__cvta_generic_to_shared(sBh);
    const uint32_t bBl = (uint32_t)__cvta_generic_to_shared(sBl);

    float acc[2][4][4];
#pragma unroll
    for (int i = 0; i < 2; i++)
#pragma unroll
        for (int j = 0; j < 4; j++)
#pragma unroll
            for (int q = 0; q < 4; q++) acc[i][j][q] = 0.f;

    const int lrow = lane & 15;         // ldmatrix row within 16
    const int lcol = (lane >> 4) * 8;   // ldmatrix col half select

    for (int k0 = 0; k0 < K; k0 += BK) {
        // stage A tile (128x32 fp32 -> bf16 hi/lo), 1024 float4 chunks
#pragma unroll
        for (int it = 0; it < 4; it++) {
            int c  = it * 256 + tid;
            int m  = c >> 3;            // 8 chunks per 32-wide row
            int kc = (c & 7) * 4;
            float4 v = *(const float4*)(A + (size_t)(row0 + m) * K + k0 + kc);
            __nv_bfloat162 h01, l01, h23, l23;
            split2(v.x, v.y, h01, l01);
            split2(v.z, v.w, h23, l23);
            *(__nv_bfloat162*)(sAh + m*SA + kc)     = h01;
            *(__nv_bfloat162*)(sAh + m*SA + kc + 2) = h23;
            *(__nv_bfloat162*)(sAl + m*SA + kc)     = l01;
            *(__nv_bfloat162*)(sAl + m*SA + kc + 2) = l23;
        }
        // stage B tile (32x64 fp32 -> bf16 hi/lo), 512 chunks
#pragma unroll
        for (int it = 0; it < 2; it++) {
            int c  = it * 256 + tid;
            int k  = c >> 4;            // 16 chunks per 64-wide row
            int nc = (c & 15) * 4;
            float4 v = *(const float4*)(B + (size_t)(k0 + k) * N + col0 + nc);
            __nv_bfloat162 h01, l01, h23, l23;
            split2(v.x, v.y, h01, l01);
            split2(v.z, v.w, h23, l23);
            *(__nv_bfloat162*)(sBh + k*SB + nc)     = h01;
            *(__nv_bfloat162*)(sBh + k*SB + nc + 2) = h23;
            *(__nv_bfloat162*)(sBl + k*SB + nc)     = l01;
            *(__nv_bfloat162*)(sBl + k*SB + nc + 2) = l23;
        }
        __syncthreads();

#pragma unroll
        for (int ks = 0; ks < 2; ks++) {
            const int kk = ks * 16;
            uint32_t ah[2][4], al[2][4], bh[4][2], bl[4][2];
#pragma unroll
            for (int i = 0; i < 2; i++) {
                uint32_t off = (uint32_t)(((wm*32 + 16*i + lrow) * SA + kk + lcol) * 2);
                ldsm4(ah[i], bAh + off);
                ldsm4(al[i], bAl + off);
            }
#pragma unroll
            for (int j2 = 0; j2 < 2; j2++) {
                uint32_t off = (uint32_t)(((kk + lrow) * SB + wn*32 + 16*j2 + lcol) * 2);
                uint32_t t[4];
                ldsm4t(t, bBh + off);
                bh[2*j2][0] = t[0]; bh[2*j2][1] = t[1];
                bh[2*j2+1][0] = t[2]; bh[2*j2+1][1] = t[3];
                ldsm4t(t, bBl + off);
                bl[2*j2][0] = t[0]; bl[2*j2][1] = t[1];
                bl[2*j2+1][0] = t[2]; bl[2*j2+1][1] = t[3];
            }
#pragma unroll
            for (int i = 0; i < 2; i++)
#pragma unroll
                for (int j = 0; j < 4; j++) {
                    mma16816(acc[i][j], ah[i], bh[j]);   // hi*hi
                    mma16816(acc[i][j], ah[i], bl[j]);   // hi*lo
                    mma16816(acc[i][j], al[i], bh[j]);   // lo*hi
                }
        }
        __syncthreads();
    }

    // epilogue
    const int group = lane >> 2, tig = lane & 3;
#pragma unroll
    for (int i = 0; i < 2; i++)
#pragma unroll
        for (int j = 0; j < 4; j++) {
            int r  = row0 + wm*32 + 16*i + group;
            int cc = col0 + wn*32 + 8*j + 2*tig;
            float b0 = bias[cc], b1 = bias[cc + 1];
            float v00 = acc[i][j][0] + b0, v01 = acc[i][j][1] + b1;
            float v10 = acc[i][j][2] + b0, v11 = acc[i][j][3] + b1;
            if (MODE == 2) {
                v00 = sigmoidf_(v00); v01 = sigmoidf_(v01);
                v10 = sigmoidf_(v10); v11 = sigmoidf_(v11);
            }
            float2 o0; o0.x = v00; o0.y = v01;
            float2 o1; o1.x = v10; o1.y = v11;
            *(float2*)(C + (size_t)r       * N + cc) = o0;
            *(float2*)(C + (size_t)(r + 8) * N + cc) = o1;
        }
}

// ---------------- elementwise gate transform ----------------
__global__ void gates_ew()
{
    int i  = blockIdx.x * blockDim.x + threadIdx.x;   // over NROWS*16 float4-groups
    int r  = i >> 4;
    int j4 = (i & 15) << 2;
    const float* gp = g_g + (size_t)r * (3*DHID);
    float4 a = *(const float4*)(gp + j4);              // pre-sigmoid fg
    float4 b = *(const float4*)(gp + DHID + j4);       // pre-sigmoid ig
    float4 c = *(const float4*)(gp + 2*DHID + j4);     // pre-tanh h
    float4 f, h;
    f.x = sigmoidf_(a.x); f.y = sigmoidf_(a.y); f.z = sigmoidf_(a.z); f.w = sigmoidf_(a.w);
    h.x = sigmoidf_(b.x) * tanhf(c.x);
    h.y = sigmoidf_(b.y) * tanhf(c.y);
    h.z = sigmoidf_(b.z) * tanhf(c.z);
    h.w = sigmoidf_(b.w) * tanhf(c.w);
    *(float4*)(g_fg + (size_t)r*DHID + j4) = f;
    *(float4*)(g_hr + (size_t)r*DHID + j4) = h;
}

// ---------------- chunked linear-recurrence scan ----------------
__global__ void scan_pass1()
{
    int b = blockIdx.x;
    int j = threadIdx.x;
    size_t base = (size_t)b * LCH * DHID + j;
    float A = 1.f, B = 0.f;
#pragma unroll 4
    for (int t = 0; t < LCH; t++) {
        size_t idx = base + (size_t)t * DHID;
        float a = g_fg[idx];
        float h = g_hr[idx];
        B = fmaf(B, a, h);
        A *= a;
    }
    g_aggA[b*DHID + j] = A;
    g_aggB[b*DHID + j] = B;
}

__global__ void scan_combine()
{
    int j = threadIdx.x;
    float c = 0.f;
#pragma unroll 4
    for (int b = 0; b < NCH; b++) {
        g_carry[b*DHID + j] = c;
        c = fmaf(c, g_aggA[b*DHID + j], g_aggB[b*DHID + j]);
    }
}

__global__ void scan_apply()
{
    int b = blockIdx.x;
    int j = threadIdx.x;
    size_t base = (size_t)b * LCH * DHID + j;
    float c = g_carry[b*DHID + j];
#pragma unroll 4
    for (int t = 0; t < LCH; t++) {
        size_t idx = base + (size_t)t * DHID;
        c = fmaf(c, g_fg[idx], g_hr[idx]);
        g_y[idx] = g_og[idx] * c;                 // og pre-sigmoided in GEMM3 epilogue
    }
}

// ---------------- launch ----------------
extern "C" void kernel_launch(void* const* d_in, const int* in_sizes, int n_in,
                              void* d_out, int out_size)
{
    const float* inputs  = (const float*)d_in[0];
    const float* W_in    = (const float*)d_in[1];
    const float* b_in    = (const float*)d_in[2];
    const float* W_gates = (const float*)d_in[3];
    const float* b_gates = (const float*)d_in[4];
    const float* W_og    = (const float*)d_in[5];
    const float* b_og    = (const float*)d_in[6];
    const float* W_c     = (const float*)d_in[7];
    const float* b_c     = (const float*)d_in[8];
    const float* W_out   = (const float*)d_in[9];
    const float* b_out   = (const float*)d_in[10];
    float* out = (float*)d_out;

    float *px, *pg, *pog, *py, *po;
    cudaGetSymbolAddress((void**)&px,  g_x);
    cudaGetSymbolAddress((void**)&pg,  g_g);
    cudaGetSymbolAddress((void**)&pog, g_og);
    cudaGetSymbolAddress((void**)&py,  g_y);
    cudaGetSymbolAddress((void**)&po,  g_o);

    dim3 blk(256);

    // 1) x = inputs @ W_in + b_in           (32768 x 512 x 512)
    gemm_tc<0><<<dim3(DMODEL/64, SEQ/128), blk>>>(inputs, W_in, b_in, px, SEQ, DMODEL, DMODEL);

    // 2) g = x' @ W_gates + b_gates         (262144 x 192 x 64)
    gemm_tc<0><<<dim3(3, NROWS/128), blk>>>(px, W_gates, b_gates, pg, NROWS, 3*DHID, DIN);

    // 3) og = sigmoid(x' @ W_og + b_og)     (262144 x 64 x 64), fused sigmoid
    gemm_tc<2><<<dim3(1, NROWS/128), blk>>>(px, W_og, b_og, pog, NROWS, DHID, DIN);

    // 4) gate nonlinearities -> fg, hr
    gates_ew<<<(NROWS*16)/256, 256>>>();

    // 5-7) chunked scan over 262144 steps x 64 columns
    scan_pass1  <<<NCH, DHID>>>();
    scan_combine<<<1,   DHID>>>();
    scan_apply  <<<NCH, DHID>>>();

    // 8) o = y @ W_c + b_c                  (262144 x 64 x 64)
    gemm_tc<0><<<dim3(1, NROWS/128), blk>>>(py, W_c, b_c, po, NROWS, DOUT, DHID);

    // 9) out = o'' @ W_out + b_out          (32768 x 512 x 512)
    gemm_tc<0><<<dim3(DMODEL/64, SEQ/128), blk>>>(po, W_out, b_out, out, SEQ, DMODEL, DMODEL);
}

// round 6
// speedup vs baseline: 2.6093x; 1.8358x over previous
#include <cuda_runtime.h>
#include <cuda_bf16.h>
#include <math.h>
#include <stdint.h>

// Problem dims (fixed by the reference)
#define SEQ    32768
#define NHEAD  8
#define DIN    64
#define DHID   64
#define DOUT   64
#define DMODEL 512                 // NHEAD*DIN
#define NROWS  (SEQ*NHEAD)         // 262144
#define LCH    128                 // scan chunk length = GEMM BM
#define NCH    (NROWS/LCH)         // 2048 chunks
#define NGRP   32                  // combine groups
#define GSZ    (NCH/NGRP)          // 64 chunks per group

// ---------------- scratch (static __device__, no allocations) ----------------
__device__ float g_x [(size_t)NROWS*DIN];       // 64 MB
__device__ float g_fg[(size_t)NROWS*DHID];      // 64 MB
__device__ float g_hr[(size_t)NROWS*DHID];      // 64 MB
__device__ float g_og[(size_t)NROWS*DHID];      // 64 MB (post-sigmoid)
__device__ float g_o [(size_t)NROWS*DOUT];      // 64 MB
__device__ float g_aggA [NCH*DHID];
__device__ float g_aggB [NCH*DHID];
__device__ float g_carry[NCH*DHID];
__device__ float g_gA[NGRP*DHID];
__device__ float g_gB[NGRP*DHID];
__device__ float g_gc[NGRP*DHID];

__device__ __forceinline__ float sigmoidf_(float x) { return 1.f / (1.f + expf(-x)); }

// ---------------- mma / ldmatrix primitives ----------------
__device__ __forceinline__ void ldsm4(uint32_t r[4], uint32_t a) {
    asm volatile("ldmatrix.sync.aligned.m8n8.x4.shared.b16 {%0,%1,%2,%3},[%4];"
        : "=r"(r[0]), "=r"(r[1]), "=r"(r[2]), "=r"(r[3]) : "r"(a));
}
__device__ __forceinline__ void ldsm4t(uint32_t r[4], uint32_t a) {
    asm volatile("ldmatrix.sync.aligned.m8n8.x4.trans.shared.b16 {%0,%1,%2,%3},[%4];"
        : "=r"(r[0]), "=r"(r[1]), "=r"(r[2]), "=r"(r[3]) : "r"(a));
}
__device__ __forceinline__ void mma16816(float c[4], const uint32_t a[4], const uint32_t b[2]) {
    asm volatile("mma.sync.aligned.m16n8k16.row.col.f32.bf16.bf16.f32 "
        "{%0,%1,%2,%3},{%4,%5,%6,%7},{%8,%9},{%0,%1,%2,%3};"
        : "+f"(c[0]), "+f"(c[1]), "+f"(c[2]), "+f"(c[3])
        : "r"(a[0]), "r"(a[1]), "r"(a[2]), "r"(a[3]), "r"(b[0]), "r"(b[1]));
}
__device__ __forceinline__ void split2(float x, float y, __nv_bfloat162& hi, __nv_bfloat162& lo) {
    __nv_bfloat16 hx = __float2bfloat16(x);
    __nv_bfloat16 hy = __float2bfloat16(y);
    __nv_bfloat16 lx = __float2bfloat16(x - __bfloat162float(hx));
    __nv_bfloat16 ly = __float2bfloat16(y - __bfloat162float(hy));
    hi.x = hx; hi.y = hy;
    lo.x = lx; lo.y = ly;
}
__device__ __forceinline__ void split1(float x, __nv_bfloat16& hi, __nv_bfloat16& lo) {
    hi = __float2bfloat16(x);
    lo = __float2bfloat16(x - __bfloat162float(hi));
}

// ============================================================================
// gemm_big: C = A(MxK) @ B(KxN) + bias, fp32 in/out, bf16 3-term split,
// double-buffered smem (dynamic), one __syncthreads per K-iter.
// BM=128, BN=64, BK=32; 256 threads = 8 warps (4 M x 2 N), warp tile 32x32.
// ============================================================================
#define GB_BM 128
#define GB_BN 64
#define GB_BK 32
#define GB_SA 40
#define GB_SB 72
#define GB_SMEM ((2*(GB_BM*GB_SA + GB_BM*GB_SA + GB_BK*GB_SB + GB_BK*GB_SB))*2)

__global__ void __launch_bounds__(256) gemm_big(
    const float* __restrict__ A, const float* __restrict__ B,
    const float* __restrict__ bias, float* __restrict__ C,
    int M, int N, int K)
{
    constexpr int BM = GB_BM, BN = GB_BN, BK = GB_BK, SA = GB_SA, SB = GB_SB;
    extern __shared__ __nv_bfloat16 dynsm[];
    __nv_bfloat16* sAh = dynsm;                    // [2][BM*SA]
    __nv_bfloat16* sAl = sAh + 2*BM*SA;
    __nv_bfloat16* sBh = sAl + 2*BM*SA;            // [2][BK*SB]
    __nv_bfloat16* sBl = sBh + 2*BK*SB;

    const int tid  = threadIdx.x;
    const int lane = tid & 31, warp = tid >> 5;
    const int wm = warp & 3, wn = warp >> 2;
    const int row0 = blockIdx.y * BM, col0 = blockIdx.x * BN;

    const uint32_t bAh = (uint32_t)__cvta_generic_to_shared(sAh);
    const uint32_t bAl = (uint32_t)__cvta_generic_to_shared(sAl);
    const uint32_t bBh = (uint32_t)__cvta_generic_to_shared(sBh);
    const uint32_t bBl = (uint32_t)__cvta_generic_to_shared(sBl);

    float acc[2][4][4];
#pragma unroll
    for (int i = 0; i < 2; i++)
#pragma unroll
        for (int j = 0; j < 4; j++)
#pragma unroll
            for (int q = 0; q < 4; q++) acc[i][j][q] = 0.f;

    const int lrow = lane & 15;
    const int lcol = (lane >> 4) * 8;

    float4 ar[4], br[2];

    auto ldg = [&](int k0) {
#pragma unroll
        for (int it = 0; it < 4; it++) {
            int c = it*256 + tid; int m = c >> 3; int kc = (c & 7) * 4;
            ar[it] = *(const float4*)(A + (size_t)(row0+m)*K + k0 + kc);
        }
#pragma unroll
        for (int it = 0; it < 2; it++) {
            int c = it*256 + tid; int k = c >> 4; int n4 = (c & 15) * 4;
            br[it] = *(const float4*)(B + (size_t)(k0+k)*N + col0 + n4);
        }
    };
    auto sts = [&](int buf) {
#pragma unroll
        for (int it = 0; it < 4; it++) {
            int c = it*256 + tid; int m = c >> 3; int kc = (c & 7) * 4;
            __nv_bfloat162 h01, l01, h23, l23;
            split2(ar[it].x, ar[it].y, h01, l01);
            split2(ar[it].z, ar[it].w, h23, l23);
            __nv_bfloat16* ph = sAh + buf*BM*SA + m*SA + kc;
            __nv_bfloat16* pl = sAl + buf*BM*SA + m*SA + kc;
            *(__nv_bfloat162*)(ph)     = h01;
            *(__nv_bfloat162*)(ph + 2) = h23;
            *(__nv_bfloat162*)(pl)     = l01;
            *(__nv_bfloat162*)(pl + 2) = l23;
        }
#pragma unroll
        for (int it = 0; it < 2; it++) {
            int c = it*256 + tid; int k = c >> 4; int n4 = (c & 15) * 4;
            __nv_bfloat162 h01, l01, h23, l23;
            split2(br[it].x, br[it].y, h01, l01);
            split2(br[it].z, br[it].w, h23, l23);
            __nv_bfloat16* ph = sBh + buf*BK*SB + k*SB + n4;
            __nv_bfloat16* pl = sBl + buf*BK*SB + k*SB + n4;
            *(__nv_bfloat162*)(ph)     = h01;
            *(__nv_bfloat162*)(ph + 2) = h23;
            *(__nv_bfloat162*)(pl)     = l01;
            *(__nv_bfloat162*)(pl + 2) = l23;
        }
    };

    ldg(0); sts(0); __syncthreads();

    const int nk = K / BK;
    for (int t = 0; t < nk; t++) {
        const int cur = t & 1;
        const bool more = (t + 1 < nk);
        if (more) ldg((t + 1) * BK);

        const uint32_t ao = (uint32_t)(cur * BM * SA * 2);
        const uint32_t bo = (uint32_t)(cur * BK * SB * 2);
#pragma unroll
        for (int ks = 0; ks < 2; ks++) {
            const int kk = ks * 16;
            uint32_t ah[2][4], al[2][4], bh[4][2], bl[4][2];
#pragma unroll
            for (int i = 0; i < 2; i++) {
                uint32_t off = (uint32_t)(((wm*32 + 16*i + lrow) * SA + kk + lcol) * 2);
                ldsm4(ah[i], bAh + ao + off);
                ldsm4(al[i], bAl + ao + off);
            }
#pragma unroll
            for (int j2 = 0; j2 < 2; j2++) {
                uint32_t off = (uint32_t)(((kk + lrow) * SB + wn*32 + 16*j2 + lcol) * 2);
                uint32_t tr[4];
                ldsm4t(tr, bBh + bo + off);
                bh[2*j2][0] = tr[0]; bh[2*j2][1] = tr[1];
                bh[2*j2+1][0] = tr[2]; bh[2*j2+1][1] = tr[3];
                ldsm4t(tr, bBl + bo + off);
                bl[2*j2][0] = tr[0]; bl[2*j2][1] = tr[1];
                bl[2*j2+1][0] = tr[2]; bl[2*j2+1][1] = tr[3];
            }
#pragma unroll
            for (int i = 0; i < 2; i++)
#pragma unroll
                for (int j = 0; j < 4; j++) {
                    mma16816(acc[i][j], ah[i], bh[j]);
                    mma16816(acc[i][j], ah[i], bl[j]);
                    mma16816(acc[i][j], al[i], bh[j]);
                }
        }
        if (more) sts(1 - cur);
        __syncthreads();
    }

    const int group = lane >> 2, tig = lane & 3;
#pragma unroll
    for (int i = 0; i < 2; i++)
#pragma unroll
        for (int j = 0; j < 4; j++) {
            int r  = row0 + wm*32 + 16*i + group;
            int cc = col0 + wn*32 + 8*j + 2*tig;
            float b0 = bias[cc], b1 = bias[cc + 1];
            float2 o0; o0.x = acc[i][j][0] + b0; o0.y = acc[i][j][1] + b1;
            float2 o1; o1.x = acc[i][j][2] + b0; o1.y = acc[i][j][3] + b1;
            *(float2*)(C + (size_t)r       * N + cc) = o0;
            *(float2*)(C + (size_t)(r + 8) * N + cc) = o1;
        }
}

// ============================================================================
// gemm_gates: fused  g = x@W_gates+b ; og = x@W_og+b ; gate nonlinearities.
// K=64 fixed. Grid x = 4 tiles:
//   tile 0: fg = sigmoid(x@Wg[:,0:64])          -> g_fg
//   tile 1: hr_m (m=0..31)  via interleaved ig/h columns -> g_hr[:,0:32]
//   tile 2: hr_m (m=32..63)                              -> g_hr[:,32:64]
//   tile 3: og = sigmoid(x@W_og)                -> g_og
// ============================================================================
__global__ void __launch_bounds__(256) gemm_gates(
    const float* __restrict__ x,
    const float* __restrict__ Wg, const float* __restrict__ bg,
    const float* __restrict__ Wog, const float* __restrict__ bog)
{
    constexpr int BM = 128, BK = 32, SA = 40, SB = 72;
    __shared__ __align__(16) __nv_bfloat16 sAh[BM*SA], sAl[BM*SA];
    __shared__ __align__(16) __nv_bfloat16 sBh[BK*SB], sBl[BK*SB];

    const int tile = blockIdx.x;
    const int tid  = threadIdx.x;
    const int lane = tid & 31, warp = tid >> 5;
    const int wm = warp & 3, wn = warp >> 2;
    const int row0 = blockIdx.y * BM;

    const uint32_t bAh = (uint32_t)__cvta_generic_to_shared(sAh);
    const uint32_t bAl = (uint32_t)__cvta_generic_to_shared(sAl);
    const uint32_t bBh = (uint32_t)__cvta_generic_to_shared(sBh);
    const uint32_t bBl = (uint32_t)__cvta_generic_to_shared(sBl);

    float acc[2][4][4];
#pragma unroll
    for (int i = 0; i < 2; i++)
#pragma unroll
        for (int j = 0; j < 4; j++)
#pragma unroll
            for (int q = 0; q < 4; q++) acc[i][j][q] = 0.f;

    const int lrow = lane & 15;
    const int lcol = (lane >> 4) * 8;
    const int base = (tile - 1) * 32;      // for tiles 1/2

    for (int k0 = 0; k0 < 64; k0 += BK) {
        // stage A (x tile 128x32, lda=64)
#pragma unroll
        for (int it = 0; it < 4; it++) {
            int c = it*256 + tid; int m = c >> 3; int kc = (c & 7) * 4;
            float4 v = *(const float4*)(x + (size_t)(row0+m)*64 + k0 + kc);
            __nv_bfloat162 h01, l01, h23, l23;
            split2(v.x, v.y, h01, l01);
            split2(v.z, v.w, h23, l23);
            *(__nv_bfloat162*)(sAh + m*SA + kc)     = h01;
            *(__nv_bfloat162*)(sAh + m*SA + kc + 2) = h23;
            *(__nv_bfloat162*)(sAl + m*SA + kc)     = l01;
            *(__nv_bfloat162*)(sAl + m*SA + kc + 2) = l23;
        }
        // stage B per tile (32 x 64 effective)
        if (tile == 0) {
#pragma unroll
            for (int it = 0; it < 2; it++) {
                int c = it*256 + tid; int k = c >> 4; int n4 = (c & 15) * 4;
                float4 v = *(const float4*)(Wg + (size_t)(k0+k)*192 + n4);
                __nv_bfloat162 h01, l01, h23, l23;
                split2(v.x, v.y, h01, l01);
                split2(v.z, v.w, h23, l23);
                *(__nv_bfloat162*)(sBh + k*SB + n4)     = h01;
                *(__nv_bfloat162*)(sBh + k*SB + n4 + 2) = h23;
                *(__nv_bfloat162*)(sBl + k*SB + n4)     = l01;
                *(__nv_bfloat162*)(sBl + k*SB + n4 + 2) = l23;
            }
        } else if (tile == 3) {
#pragma unroll
            for (int it = 0; it < 2; it++) {
                int c = it*256 + tid; int k = c >> 4; int n4 = (c & 15) * 4;
                float4 v = *(const float4*)(Wog + (size_t)(k0+k)*64 + n4);
                __nv_bfloat162 h01, l01, h23, l23;
                split2(v.x, v.y, h01, l01);
                split2(v.z, v.w, h23, l23);
                *(__nv_bfloat162*)(sBh + k*SB + n4)     = h01;
                *(__nv_bfloat162*)(sBh + k*SB + n4 + 2) = h23;
                *(__nv_bfloat162*)(sBl + k*SB + n4)     = l01;
                *(__nv_bfloat162*)(sBl + k*SB + n4 + 2) = l23;
            }
        } else {
            // interleave: B'[k][2m] = Wg[k][64+base+m], B'[k][2m+1] = Wg[k][128+base+m]
#pragma unroll
            for (int it = 0; it < 4; it++) {
                int c = it*256 + tid; int k = c >> 5; int m = c & 31;
                float a  = Wg[(size_t)(k0+k)*192 + 64  + base + m];
                float b2 = Wg[(size_t)(k0+k)*192 + 128 + base + m];
                __nv_bfloat162 h, l;
                split2(a, b2, h, l);
                *(__nv_bfloat162*)(sBh + k*SB + 2*m) = h;
                *(__nv_bfloat162*)(sBl + k*SB + 2*m) = l;
            }
        }
        __syncthreads();

#pragma unroll
        for (int ks = 0; ks < 2; ks++) {
            const int kk = ks * 16;
            uint32_t ah[2][4], al[2][4], bh[4][2], bl[4][2];
#pragma unroll
            for (int i = 0; i < 2; i++) {
                uint32_t off = (uint32_t)(((wm*32 + 16*i + lrow) * SA + kk + lcol) * 2);
                ldsm4(ah[i], bAh + off);
                ldsm4(al[i], bAl + off);
            }
#pragma unroll
            for (int j2 = 0; j2 < 2; j2++) {
                uint32_t off = (uint32_t)(((kk + lrow) * SB + wn*32 + 16*j2 + lcol) * 2);
                uint32_t tr[4];
                ldsm4t(tr, bBh + off);
                bh[2*j2][0] = tr[0]; bh[2*j2][1] = tr[1];
                bh[2*j2+1][0] = tr[2]; bh[2*j2+1][1] = tr[3];
                ldsm4t(tr, bBl + off);
                bl[2*j2][0] = tr[0]; bl[2*j2][1] = tr[1];
                bl[2*j2+1][0] = tr[2]; bl[2*j2+1][1] = tr[3];
            }
#pragma unroll
            for (int i = 0; i < 2; i++)
#pragma unroll
                for (int j = 0; j < 4; j++) {
                    mma16816(acc[i][j], ah[i], bh[j]);
                    mma16816(acc[i][j], ah[i], bl[j]);
                    mma16816(acc[i][j], al[i], bh[j]);
                }
        }
        __syncthreads();
    }

    // epilogue
    const int group = lane >> 2, tig = lane & 3;
#pragma unroll
    for (int i = 0; i < 2; i++)
#pragma unroll
        for (int j = 0; j < 4; j++) {
            int r  = row0 + wm*32 + 16*i + group;
            int cc = wn*32 + 8*j + 2*tig;
            if (tile == 0) {
                float b0 = bg[cc], b1 = bg[cc+1];
                float2 o0; o0.x = sigmoidf_(acc[i][j][0] + b0); o0.y = sigmoidf_(acc[i][j][1] + b1);
                float2 o1; o1.x = sigmoidf_(acc[i][j][2] + b0); o1.y = sigmoidf_(acc[i][j][3] + b1);
                *(float2*)(g_fg + (size_t)r       * DHID + cc) = o0;
                *(float2*)(g_fg + (size_t)(r + 8) * DHID + cc) = o1;
            } else if (tile == 3) {
                float b0 = bog[cc], b1 = bog[cc+1];
                float2 o0; o0.x = sigmoidf_(acc[i][j][0] + b0); o0.y = sigmoidf_(acc[i][j][1] + b1);
                float2 o1; o1.x = sigmoidf_(acc[i][j][2] + b0); o1.y = sigmoidf_(acc[i][j][3] + b1);
                *(float2*)(g_og + (size_t)r       * DHID + cc) = o0;
                *(float2*)(g_og + (size_t)(r + 8) * DHID + cc) = o1;
            } else {
                int mg = base + (cc >> 1);
                float b0 = bg[64 + mg], b1 = bg[128 + mg];
                float hr0 = sigmoidf_(acc[i][j][0] + b0) * tanhf(acc[i][j][1] + b1);
                float hr1 = sigmoidf_(acc[i][j][2] + b0) * tanhf(acc[i][j][3] + b1);
                g_hr[(size_t)r       * DHID + mg] = hr0;
                g_hr[(size_t)(r + 8) * DHID + mg] = hr1;
            }
        }
}

// ============================================================================
// scan: chunk aggregates, hierarchical combine, then fused apply+GEMM4
// ============================================================================
__global__ void scan_pass1()
{
    int b = blockIdx.x;
    int j = threadIdx.x;
    size_t base = (size_t)b * LCH * DHID + j;
    float A = 1.f, B = 0.f;
#pragma unroll 8
    for (int t = 0; t < LCH; t++) {
        size_t idx = base + (size_t)t * DHID;
        float a = g_fg[idx];
        float h = g_hr[idx];
        B = fmaf(B, a, h);
        A *= a;
    }
    g_aggA[b*DHID + j] = A;
    g_aggB[b*DHID + j] = B;
}

__global__ void combine1()   // 32 blocks x 64 thr: group aggregates
{
    int g = blockIdx.x, j = threadIdx.x;
    float A = 1.f, B = 0.f;
#pragma unroll 8
    for (int c = 0; c < GSZ; c++) {
        int idx = (g*GSZ + c)*DHID + j;
        float a = g_aggA[idx], b = g_aggB[idx];
        B = fmaf(B, a, b);
        A *= a;
    }
    g_gA[g*DHID + j] = A;
    g_gB[g*DHID + j] = B;
}

__global__ void combine2()   // 1 block x 64 thr: serial over 32 groups
{
    int j = threadIdx.x;
    float c = 0.f;
#pragma unroll
    for (int g = 0; g < NGRP; g++) {
        g_gc[g*DHID + j] = c;
        c = fmaf(c, g_gA[g*DHID + j], g_gB[g*DHID + j]);
    }
}

__global__ void combine3()   // 32 blocks x 64 thr: chunk carries within group
{
    int g = blockIdx.x, j = threadIdx.x;
    float c = g_gc[g*DHID + j];
#pragma unroll 8
    for (int cc = 0; cc < GSZ; cc++) {
        int idx = (g*GSZ + cc)*DHID + j;
        g_carry[idx] = c;
        c = fmaf(c, g_aggA[idx], g_aggB[idx]);
    }
}

// fused: per-chunk scan -> y = og*c (split bf16 into smem) -> o = y@W_c + b_c
#define LA_SY 72
#define LA_SW 72
#define LA_SMEM ((128*LA_SY*2 + 64*LA_SW*2)*2)

__global__ void __launch_bounds__(256) lstm_apply_gemm(
    const float* __restrict__ Wc, const float* __restrict__ bc)
{
    extern __shared__ __nv_bfloat16 dynsm2[];
    __nv_bfloat16* sYh = dynsm2;                 // [128][72]
    __nv_bfloat16* sYl = sYh + 128*LA_SY;
    __nv_bfloat16* sWh = sYl + 128*LA_SY;        // [64][72]
    __nv_bfloat16* sWl = sWh + 64*LA_SW;

    const int b   = blockIdx.x;
    const int tid = threadIdx.x;
    const int lane = tid & 31, warp = tid >> 5;
    const int wm = warp & 3, wn = warp >> 2;

    // stage W_c (64x64)
#pragma unroll
    for (int it = 0; it < 4; it++) {
        int c = it*256 + tid; int k = c >> 4; int n4 = (c & 15) * 4;
        float4 v = *(const float4*)(Wc + (size_t)k*64 + n4);
        __nv_bfloat162 h01, l01, h23, l23;
        split2(v.x, v.y, h01, l01);
        split2(v.z, v.w, h23, l23);
        *(__nv_bfloat162*)(sWh + k*LA_SW + n4)     = h01;
        *(__nv_bfloat162*)(sWh + k*LA_SW + n4 + 2) = h23;
        *(__nv_bfloat162*)(sWl + k*LA_SW + n4)     = l01;
        *(__nv_bfloat162*)(sWl + k*LA_SW + n4 + 2) = l23;
    }

    // serial scan for this chunk: threads 0..63 = columns
    if (tid < 64) {
        int j = tid;
        float c = g_carry[b*DHID + j];
        size_t base = (size_t)b * LCH * DHID + j;
#pragma unroll 8
        for (int t = 0; t < LCH; t++) {
            size_t idx = base + (size_t)t * DHID;
            c = fmaf(c, g_fg[idx], g_hr[idx]);
            float y = g_og[idx] * c;
            __nv_bfloat16 yh, yl;
            split1(y, yh, yl);
            sYh[t*LA_SY + j] = yh;
            sYl[t*LA_SY + j] = yl;
        }
    }
    __syncthreads();

    // mma: o(128x64) = y(128x64) @ Wc(64x64)
    const uint32_t bYh = (uint32_t)__cvta_generic_to_shared(sYh);
    const uint32_t bYl = (uint32_t)__cvta_generic_to_shared(sYl);
    const uint32_t bWh = (uint32_t)__cvta_generic_to_shared(sWh);
    const uint32_t bWl = (uint32_t)__cvta_generic_to_shared(sWl);

    float acc[2][4][4];
#pragma unroll
    for (int i = 0; i < 2; i++)
#pragma unroll
        for (int j = 0; j < 4; j++)
#pragma unroll
            for (int q = 0; q < 4; q++) acc[i][j][q] = 0.f;

    const int lrow = lane & 15;
    const int lcol = (lane >> 4) * 8;

#pragma unroll
    for (int ks = 0; ks < 4; ks++) {
        const int kk = ks * 16;
        uint32_t ah[2][4], al[2][4], bh[4][2], bl[4][2];
#pragma unroll
        for (int i = 0; i < 2; i++) {
            uint32_t off = (uint32_t)(((wm*32 + 16*i + lrow) * LA_SY + kk + lcol) * 2);
            ldsm4(ah[i], bYh + off);
            ldsm4(al[i], bYl + off);
        }
#pragma unroll
        for (int j2 = 0; j2 < 2; j2++) {
            uint32_t off = (uint32_t)(((kk + lrow) * LA_SW + wn*32 + 16*j2 + lcol) * 2);
            uint32_t tr[4];
            ldsm4t(tr, bWh + off);
            bh[2*j2][0] = tr[0]; bh[2*j2][1] = tr[1];
            bh[2*j2+1][0] = tr[2]; bh[2*j2+1][1] = tr[3];
            ldsm4t(tr, bWl + off);
            bl[2*j2][0] = tr[0]; bl[2*j2][1] = tr[1];
            bl[2*j2+1][0] = tr[2]; bl[2*j2+1][1] = tr[3];
        }
#pragma unroll
        for (int i = 0; i < 2; i++)
#pragma unroll
            for (int j = 0; j < 4; j++) {
                mma16816(acc[i][j], ah[i], bh[j]);
                mma16816(acc[i][j], ah[i], bl[j]);
                mma16816(acc[i][j], al[i], bh[j]);
            }
    }

    const int group = lane >> 2, tig = lane & 3;
#pragma unroll
    for (int i = 0; i < 2; i++)
#pragma unroll
        for (int j = 0; j < 4; j++) {
            int r  = b*128 + wm*32 + 16*i + group;
            int cc = wn*32 + 8*j + 2*tig;
            float b0 = bc[cc], b1 = bc[cc+1];
            float2 o0; o0.x = acc[i][j][0] + b0; o0.y = acc[i][j][1] + b1;
            float2 o1; o1.x = acc[i][j][2] + b0; o1.y = acc[i][j][3] + b1;
            *(float2*)(g_o + (size_t)r       * DOUT + cc) = o0;
            *(float2*)(g_o + (size_t)(r + 8) * DOUT + cc) = o1;
        }
}

// ---------------- launch ----------------
extern "C" void kernel_launch(void* const* d_in, const int* in_sizes, int n_in,
                              void* d_out, int out_size)
{
    const float* inputs  = (const float*)d_in[0];
    const float* W_in    = (const float*)d_in[1];
    const float* b_in    = (const float*)d_in[2];
    const float* W_gates = (const float*)d_in[3];
    const float* b_gates = (const float*)d_in[4];
    const float* W_og    = (const float*)d_in[5];
    const float* b_og    = (const float*)d_in[6];
    const float* W_c     = (const float*)d_in[7];
    const float* b_c     = (const float*)d_in[8];
    const float* W_out   = (const float*)d_in[9];
    const float* b_out   = (const float*)d_in[10];
    float* out = (float*)d_out;

    float *px, *po;
    cudaGetSymbolAddress((void**)&px, g_x);
    cudaGetSymbolAddress((void**)&po, g_o);

    cudaFuncSetAttribute(gemm_big, cudaFuncAttributeMaxDynamicSharedMemorySize, GB_SMEM);
    cudaFuncSetAttribute(lstm_apply_gemm, cudaFuncAttributeMaxDynamicSharedMemorySize, LA_SMEM);

    dim3 blk(256);

    // 1) x = inputs @ W_in + b_in           (32768 x 512 x 512)
    gemm_big<<<dim3(DMODEL/64, SEQ/128), blk, GB_SMEM>>>(
        inputs, W_in, b_in, px, SEQ, DMODEL, DMODEL);

    // 2) fused gates: fg, hr, og           (262144 rows, K=64)
    gemm_gates<<<dim3(4, NROWS/128), blk>>>(px, W_gates, b_gates, W_og, b_og);

    // 3) chunk aggregates + hierarchical combine
    scan_pass1<<<NCH, DHID>>>();
    combine1<<<NGRP, DHID>>>();
    combine2<<<1, DHID>>>();
    combine3<<<NGRP, DHID>>>();

    // 4) fused scan-apply + o = y @ W_c + b_c
    lstm_apply_gemm<<<NCH, blk, LA_SMEM>>>(W_c, b_c);

    // 5) out = o @ W_out + b_out            (32768 x 512 x 512)
    gemm_big<<<dim3(DMODEL/64, SEQ/128), blk, GB_SMEM>>>(
        po, W_out, b_out, out, SEQ, DMODEL, DMODEL);
}